// round 5
// baseline (speedup 1.0000x reference)
#include <cuda_runtime.h>
#include <math.h>
#include <stdint.h>

#define BATCH 8
#define CH    64
#define HH    256
#define WW    256
#define HW    65536
#define P     16
#define OC    64
#define NUNSEL 48
#define OUTC  112   // OC + (CH - P)
#define NBINS 256

// ---------------- device scratch (no allocation allowed) ----------------
__device__ double g_ent[BATCH * CH];
__device__ int    g_sel[BATCH][P];
__device__ int    g_unsel[BATCH][NUNSEL];

// ===================================================================
// Kernel 1: per-(b,c) min/max + privatized 256-bin histogram + entropy
// one block per (b,c). dynamic smem: 256 threads * 256 bins * u16 = 128KB
// ===================================================================
__global__ __launch_bounds__(256) void hist_entropy_kernel(const float* __restrict__ x) {
    extern __shared__ unsigned short s_hist[];   // [tid][bin], 256*256
    __shared__ float  s_mn[256];
    __shared__ float  s_mx[256];
    __shared__ double s_d[256];

    const int bc  = blockIdx.x;          // 0..511
    const int tid = threadIdx.x;
    const float4* xp = (const float4*)(x + (size_t)bc * HW);

    // zero private histograms (65536 u16 = 8192 uint4)
    {
        uint4* h4 = (uint4*)s_hist;
        #pragma unroll
        for (int i = 0; i < 32; i++) {
            h4[tid + i * 256] = make_uint4(0u, 0u, 0u, 0u);
        }
    }

    // ---- pass 1: min/max ----
    float mn =  3.4e38f, mx = -3.4e38f;
    for (int i = tid; i < HW / 4; i += 256) {
        float4 v = xp[i];
        mn = fminf(mn, fminf(fminf(v.x, v.y), fminf(v.z, v.w)));
        mx = fmaxf(mx, fmaxf(fmaxf(v.x, v.y), fmaxf(v.z, v.w)));
    }
    s_mn[tid] = mn; s_mx[tid] = mx;
    __syncthreads();
    for (int s = 128; s > 0; s >>= 1) {
        if (tid < s) {
            s_mn[tid] = fminf(s_mn[tid], s_mn[tid + s]);
            s_mx[tid] = fmaxf(s_mx[tid], s_mx[tid + s]);
        }
        __syncthreads();
    }
    mn = s_mn[0];
    mx = s_mx[0];
    // (last loop iteration ended with __syncthreads; s_hist zeros also visible)

    // ---- pass 2: binning into private histogram (no atomics) ----
    // Must match XLA bit-exactly: (x - min) / ((max - min) + 1e-8f), *256, trunc, clip.
    const float den = (mx - mn) + 1e-8f;
    unsigned short* my = s_hist + tid * NBINS;
    for (int i = tid; i < HW / 4; i += 256) {
        float4 v = xp[i];
        float f0 = __fdiv_rn(v.x - mn, den);
        float f1 = __fdiv_rn(v.y - mn, den);
        float f2 = __fdiv_rn(v.z - mn, den);
        float f3 = __fdiv_rn(v.w - mn, den);
        int b0 = (int)(f0 * 256.0f); b0 = min(max(b0, 0), NBINS - 1);
        int b1 = (int)(f1 * 256.0f); b1 = min(max(b1, 0), NBINS - 1);
        int b2 = (int)(f2 * 256.0f); b2 = min(max(b2, 0), NBINS - 1);
        int b3 = (int)(f3 * 256.0f); b3 = min(max(b3, 0), NBINS - 1);
        my[b0]++; my[b1]++; my[b2]++; my[b3]++;
    }
    __syncthreads();

    // ---- flush: count for bin 'tid' = sum over all 256 private copies ----
    unsigned int cnt = 0;
    #pragma unroll 8
    for (int t = 0; t < 256; t++) cnt += (unsigned int)s_hist[t * NBINS + tid];

    // ---- entropy (double) ----
    double h = (cnt > 0) ? (double)cnt : 1e-8;
    s_d[tid] = h;
    __syncthreads();
    for (int s = 128; s > 0; s >>= 1) {
        if (tid < s) s_d[tid] += s_d[tid + s];
        __syncthreads();
    }
    double sum = s_d[0];
    __syncthreads();
    double p = h / sum;
    s_d[tid] = -p * log(p + 1e-8);
    __syncthreads();
    for (int s = 128; s > 0; s >>= 1) {
        if (tid < s) s_d[tid] += s_d[tid + s];
        __syncthreads();
    }
    if (tid == 0) g_ent[bc] = s_d[0];
}

// ===================================================================
// Kernel 2: top-16 per batch (strict >, ties -> lowest index, = jax top_k)
// ===================================================================
__global__ void topk_kernel() {
    int b = threadIdx.x;
    if (b >= BATCH) return;
    bool used[CH];
    #pragma unroll
    for (int c = 0; c < CH; c++) used[c] = false;
    for (int p = 0; p < P; p++) {
        int best = -1;
        double bv = -1e300;
        for (int c = 0; c < CH; c++) {
            if (!used[c]) {
                double e = g_ent[b * CH + c];
                if (e > bv) { bv = e; best = c; }
            }
        }
        g_sel[b][p] = best;
        used[best] = true;
    }
    int j = 0;
    for (int c = 0; c < CH; c++)
        if (!used[c]) g_unsel[b][j++] = c;
}

// ===================================================================
// Kernel 3: copy untouched channels (ascending order) to out[:, 64:112]
// ===================================================================
__global__ __launch_bounds__(256) void copy_untouched_kernel(const float* __restrict__ x,
                                                             float* __restrict__ out) {
    const int j = blockIdx.y;            // 0..383
    const int b = j / NUNSEL;
    const int u = j - b * NUNSEL;
    const int src_c = g_unsel[b][u];
    const float4* s = (const float4*)(x + ((size_t)(b * CH + src_c)) * HW);
    float4*       d = (float4*)(out + ((size_t)(b * OUTC + OC + u)) * HW);
    const int i = blockIdx.x * 256 + threadIdx.x;   // gridDim.x = 64 -> 16384 f4
    d[i] = s[i];
}

// ===================================================================
// Kernel 4: direct 3x3 conv, 16 selected in-ch -> 64 out-ch, pad 1
// block = one (batch, 32x32 tile); smem: input tile 16x34x34 + all weights
// each thread: 4 pixels (col, stride 8 rows) x 16 out-ch register tile
// ===================================================================
#define SIN_ELEMS (16 * 34 * 34)   // 18496
#define SW_ELEMS  (OC * P * 9)     // 9216
#define CONV_SMEM ((SIN_ELEMS + SW_ELEMS) * 4)

__global__ __launch_bounds__(256) void conv_kernel(const float* __restrict__ x,
                                                   const float* __restrict__ wgt,
                                                   const float* __restrict__ bias,
                                                   float* __restrict__ out) {
    extern __shared__ float smem[];
    float* s_in = smem;            // [ic][34][34]
    float* s_w  = smem + SIN_ELEMS;

    const int b       = blockIdx.y;
    const int tileIdx = blockIdx.x;             // 0..63
    const int ty0 = (tileIdx >> 3) << 5;
    const int tx0 = (tileIdx & 7) << 5;
    const int tid = threadIdx.x;

    // stage weights
    for (int i = tid; i < SW_ELEMS; i += 256) s_w[i] = wgt[i];

    // stage input tile with halo (zero padding at image borders)
    for (int i = tid; i < SIN_ELEMS; i += 256) {
        const int ic = i / (34 * 34);
        const int r  = i - ic * (34 * 34);
        const int yy = r / 34;
        const int xx = r - yy * 34;
        const int gy = ty0 + yy - 1;
        const int gx = tx0 + xx - 1;
        float v = 0.0f;
        if (gy >= 0 && gy < HH && gx >= 0 && gx < WW) {
            const int c = g_sel[b][ic];
            v = __ldg(&x[((size_t)(b * CH + c)) * HW + gy * WW + gx]);
        }
        s_in[i] = v;
    }
    __syncthreads();

    const int tx = tid & 31;
    const int ty = tid >> 5;    // 0..7

    for (int ocg = 0; ocg < OC; ocg += 16) {
        float acc[4][16];
        #pragma unroll
        for (int o = 0; o < 16; o++) {
            const float bv = __ldg(&bias[ocg + o]);
            #pragma unroll
            for (int r = 0; r < 4; r++) acc[r][o] = bv;
        }

        for (int ic = 0; ic < P; ic++) {
            const float* si = s_in + ic * (34 * 34);
            const float* wb = s_w + ocg * (P * 9) + ic * 9;
            #pragma unroll
            for (int ky = 0; ky < 3; ky++) {
                #pragma unroll
                for (int kx = 0; kx < 3; kx++) {
                    float w[16];
                    #pragma unroll
                    for (int o = 0; o < 16; o++) w[o] = wb[o * (P * 9) + ky * 3 + kx];
                    #pragma unroll
                    for (int r = 0; r < 4; r++) {
                        const float v = si[(ty + 8 * r + ky) * 34 + (tx + kx)];
                        #pragma unroll
                        for (int o = 0; o < 16; o++) acc[r][o] = fmaf(v, w[o], acc[r][o]);
                    }
                }
            }
        }

        // store (coalesced over tx)
        #pragma unroll
        for (int o = 0; o < 16; o++) {
            float* ob = out + ((size_t)(b * OUTC + ocg + o)) * HW;
            #pragma unroll
            for (int r = 0; r < 4; r++) {
                ob[(ty0 + ty + 8 * r) * WW + (tx0 + tx)] = acc[r][o];
            }
        }
    }
}

// ===================================================================
extern "C" void kernel_launch(void* const* d_in, const int* in_sizes, int n_in,
                              void* d_out, int out_size) {
    const float* x    = (const float*)d_in[0];   // [8,64,256,256]
    const float* wgt  = (const float*)d_in[1];   // [64,16,3,3]
    const float* bias = (const float*)d_in[2];   // [64]
    float* out = (float*)d_out;                  // [8,112,256,256]

    cudaFuncSetAttribute(hist_entropy_kernel,
                         cudaFuncAttributeMaxDynamicSharedMemorySize, 256 * NBINS * 2);
    cudaFuncSetAttribute(conv_kernel,
                         cudaFuncAttributeMaxDynamicSharedMemorySize, CONV_SMEM);

    hist_entropy_kernel<<<BATCH * CH, 256, 256 * NBINS * 2>>>(x);
    topk_kernel<<<1, 32>>>();
    copy_untouched_kernel<<<dim3(64, BATCH * NUNSEL), 256>>>(x, out);
    conv_kernel<<<dim3(64, BATCH), 256, CONV_SMEM>>>(x, wgt, bias, out);
}

// round 8
// speedup vs baseline: 1.0819x; 1.0819x over previous
#include <cuda_runtime.h>
#include <math.h>
#include <stdint.h>

#define BATCH 8
#define CH    64
#define HH    256
#define WW    256
#define HW    65536
#define P     16
#define OC    64
#define NUNSEL 48
#define OUTC  112   // OC + (CH - P)
#define NBINS 256

typedef unsigned long long ull;

// ---------------- device scratch (no allocation allowed) ----------------
__device__ double g_ent[BATCH * CH];
__device__ int    g_sel[BATCH][P];
__device__ int    g_unsel[BATCH][NUNSEL];

// ===================================================================
// Kernel 1: per-(b,c) min/max + privatized 256-bin histogram + entropy
// one block per (b,c). dynamic smem: 256 threads * 256 bins * u16 = 128KB
// bank-conflict-free via per-thread bin rotation: bin' = (bin + 2*tid)&255
//   -> bank = ((bin>>1) + tid) & 31 : distinct per lane when bins equal.
// ===================================================================
__global__ __launch_bounds__(256) void hist_entropy_kernel(const float* __restrict__ x) {
    extern __shared__ unsigned short s_hist[];   // [tid][rot(bin)], 256*256
    __shared__ float  s_mn[256];
    __shared__ float  s_mx[256];
    __shared__ double s_d[256];

    const int bc  = blockIdx.x;          // 0..511
    const int tid = threadIdx.x;
    const float4* xp = (const float4*)(x + (size_t)bc * HW);

    // zero private histograms (65536 u16 = 8192 uint4)
    {
        uint4* h4 = (uint4*)s_hist;
        #pragma unroll
        for (int i = 0; i < 32; i++) h4[tid + i * 256] = make_uint4(0u, 0u, 0u, 0u);
    }

    // ---- pass 1: min/max (2-way unrolled for MLP) ----
    float mn =  3.4e38f, mx = -3.4e38f;
    for (int i = tid; i < HW / 4; i += 512) {
        float4 a = xp[i];
        float4 b = xp[i + 256];
        mn = fminf(mn, fminf(fminf(a.x, a.y), fminf(a.z, a.w)));
        mx = fmaxf(mx, fmaxf(fmaxf(a.x, a.y), fmaxf(a.z, a.w)));
        mn = fminf(mn, fminf(fminf(b.x, b.y), fminf(b.z, b.w)));
        mx = fmaxf(mx, fmaxf(fmaxf(b.x, b.y), fmaxf(b.z, b.w)));
    }
    s_mn[tid] = mn; s_mx[tid] = mx;
    __syncthreads();
    for (int s = 128; s > 0; s >>= 1) {
        if (tid < s) {
            s_mn[tid] = fminf(s_mn[tid], s_mn[tid + s]);
            s_mx[tid] = fmaxf(s_mx[tid], s_mx[tid + s]);
        }
        __syncthreads();
    }
    mn = s_mn[0];
    mx = s_mx[0];

    // ---- pass 2: binning into swizzled private histogram (no atomics) ----
    // Must match XLA bit-exactly: (x - min) / ((max - min) + 1e-8f), *256, trunc, clip.
    const float den = (mx - mn) + 1e-8f;
    const int rot = tid << 1;
    unsigned short* my = s_hist + tid * NBINS;
    for (int i = tid; i < HW / 4; i += 512) {
        float4 va = xp[i];
        float4 vb = xp[i + 256];
        float f0 = __fdiv_rn(va.x - mn, den);
        float f1 = __fdiv_rn(va.y - mn, den);
        float f2 = __fdiv_rn(va.z - mn, den);
        float f3 = __fdiv_rn(va.w - mn, den);
        float f4 = __fdiv_rn(vb.x - mn, den);
        float f5 = __fdiv_rn(vb.y - mn, den);
        float f6 = __fdiv_rn(vb.z - mn, den);
        float f7 = __fdiv_rn(vb.w - mn, den);
        int b0 = min(max((int)(f0 * 256.0f), 0), NBINS - 1);
        int b1 = min(max((int)(f1 * 256.0f), 0), NBINS - 1);
        int b2 = min(max((int)(f2 * 256.0f), 0), NBINS - 1);
        int b3 = min(max((int)(f3 * 256.0f), 0), NBINS - 1);
        int b4 = min(max((int)(f4 * 256.0f), 0), NBINS - 1);
        int b5 = min(max((int)(f5 * 256.0f), 0), NBINS - 1);
        int b6 = min(max((int)(f6 * 256.0f), 0), NBINS - 1);
        int b7 = min(max((int)(f7 * 256.0f), 0), NBINS - 1);
        my[(b0 + rot) & 255]++;
        my[(b1 + rot) & 255]++;
        my[(b2 + rot) & 255]++;
        my[(b3 + rot) & 255]++;
        my[(b4 + rot) & 255]++;
        my[(b5 + rot) & 255]++;
        my[(b6 + rot) & 255]++;
        my[(b7 + rot) & 255]++;
    }
    __syncthreads();

    // ---- flush: count for bin 'tid' = sum over all 256 private (rotated) copies ----
    unsigned int cnt = 0;
    #pragma unroll 8
    for (int t = 0; t < 256; t++)
        cnt += (unsigned int)s_hist[t * NBINS + ((tid + (t << 1)) & 255)];

    // ---- entropy (double; matches f32-reference ordering with margin) ----
    double h = (cnt > 0) ? (double)cnt : 1e-8;
    s_d[tid] = h;
    __syncthreads();
    for (int s = 128; s > 0; s >>= 1) {
        if (tid < s) s_d[tid] += s_d[tid + s];
        __syncthreads();
    }
    double sum = s_d[0];
    __syncthreads();
    double p = h / sum;
    s_d[tid] = -p * log(p + 1e-8);
    __syncthreads();
    for (int s = 128; s > 0; s >>= 1) {
        if (tid < s) s_d[tid] += s_d[tid + s];
        __syncthreads();
    }
    if (tid == 0) g_ent[bc] = s_d[0];
}

// ===================================================================
// Kernel 2: top-16 per batch (strict >, ties -> lowest index, = jax top_k)
// ===================================================================
__global__ void topk_kernel() {
    int b = threadIdx.x;
    if (b >= BATCH) return;
    bool used[CH];
    #pragma unroll
    for (int c = 0; c < CH; c++) used[c] = false;
    for (int p = 0; p < P; p++) {
        int best = -1;
        double bv = -1e300;
        for (int c = 0; c < CH; c++) {
            if (!used[c]) {
                double e = g_ent[b * CH + c];
                if (e > bv) { bv = e; best = c; }
            }
        }
        g_sel[b][p] = best;
        used[best] = true;
    }
    int j = 0;
    for (int c = 0; c < CH; c++)
        if (!used[c]) g_unsel[b][j++] = c;
}

// ===================================================================
// Kernel 3: copy untouched channels (ascending order) to out[:, 64:112]
// ===================================================================
__global__ __launch_bounds__(256) void copy_untouched_kernel(const float* __restrict__ x,
                                                             float* __restrict__ out) {
    const int j = blockIdx.y;            // 0..383
    const int b = j / NUNSEL;
    const int u = j - b * NUNSEL;
    const int src_c = g_unsel[b][u];
    const float4* s = (const float4*)(x + ((size_t)(b * CH + src_c)) * HW);
    float4*       d = (float4*)(out + ((size_t)(b * OUTC + OC + u)) * HW);
    const int i = blockIdx.x * 256 + threadIdx.x;   // gridDim.x = 64 -> 16384 f4
    d[i] = s[i];
}

// ===================================================================
// Kernel 4: direct 3x3 conv via packed fma.rn.f32x2 (2 oc per FFMA2)
// block = one (batch, 32x32 tile). Each thread: 4 consecutive rows x 16 oc.
// smem: input 16x34x34 + weights transposed to [144][64] (oc contiguous,
// so one LDS.128 yields two ready f32x2 weight pairs).
// ===================================================================
#define SIN_ELEMS (16 * 34 * 34)   // 18496
#define SW_ELEMS  (144 * 64)       // 9216
#define CONV_SMEM ((SIN_ELEMS + SW_ELEMS) * 4)

__global__ __launch_bounds__(256, 2) void conv_kernel(const float* __restrict__ x,
                                                      const float* __restrict__ wgt,
                                                      const float* __restrict__ bias,
                                                      float* __restrict__ out) {
    extern __shared__ float smem[];
    float* s_in = smem;            // [ic][34][34]
    float* s_w  = smem + SIN_ELEMS;  // [(ic*9+ky*3+kx)][oc]

    const int b       = blockIdx.y;
    const int tileIdx = blockIdx.x;             // 0..63
    const int ty0 = (tileIdx >> 3) << 5;
    const int tx0 = (tileIdx & 7) << 5;
    const int tid = threadIdx.x;

    // stage weights transposed: s_w[r*64 + oc] = wgt[oc*144 + r]
    for (int i = tid; i < SW_ELEMS; i += 256) {
        const int r  = i >> 6;
        const int oc = i & 63;
        s_w[i] = __ldg(&wgt[oc * 144 + r]);
    }

    // stage input tile with halo (zero padding at image borders)
    for (int i = tid; i < SIN_ELEMS; i += 256) {
        const int ic = i / (34 * 34);
        const int r  = i - ic * (34 * 34);
        const int yy = r / 34;
        const int xx = r - yy * 34;
        const int gy = ty0 + yy - 1;
        const int gx = tx0 + xx - 1;
        float v = 0.0f;
        if (gy >= 0 && gy < HH && gx >= 0 && gx < WW) {
            const int c = g_sel[b][ic];
            v = __ldg(&x[((size_t)(b * CH + c)) * HW + gy * WW + gx]);
        }
        s_in[i] = v;
    }
    __syncthreads();

    const int tx    = tid & 31;
    const int warp  = tid >> 5;     // 0..7
    const int ybase = warp << 2;    // output rows ybase..ybase+3 (tile-local)

    for (int ocg = 0; ocg < OC; ocg += 16) {
        // acc[r][o] holds oc = ocg+2o (low half) and ocg+2o+1 (high half)
        ull acc[4][8];
        {
            const ull* bp = (const ull*)(bias + ocg);   // 8B-aligned (ocg%16==0)
            #pragma unroll
            for (int o = 0; o < 8; o++) {
                const ull bb = __ldg(&bp[o]);
                #pragma unroll
                for (int r = 0; r < 4; r++) acc[r][o] = bb;
            }
        }

        for (int ic = 0; ic < P; ic++) {
            const float* si = s_in + ic * (34 * 34);
            // preload + duplicate-pack the 6x3 input window (rows reused across ky)
            ull vinp[6][3];
            #pragma unroll
            for (int j = 0; j < 6; j++) {
                #pragma unroll
                for (int kx = 0; kx < 3; kx++) {
                    const float v = si[(ybase + j) * 34 + tx + kx];
                    asm("mov.b64 %0, {%1, %1};" : "=l"(vinp[j][kx]) : "f"(v));
                }
            }
            const float* wb = s_w + ic * 9 * 64 + ocg;
            #pragma unroll
            for (int ky = 0; ky < 3; ky++) {
                #pragma unroll
                for (int kx = 0; kx < 3; kx++) {
                    // 16 weights (8 f32x2 pairs) via 4 broadcast LDS.128
                    const ulonglong2* wp = (const ulonglong2*)(wb + (ky * 3 + kx) * 64);
                    ull w[8];
                    #pragma unroll
                    for (int q = 0; q < 4; q++) {
                        ulonglong2 wv = wp[q];
                        w[2 * q]     = wv.x;
                        w[2 * q + 1] = wv.y;
                    }
                    #pragma unroll
                    for (int r = 0; r < 4; r++) {
                        const ull vv = vinp[r + ky][kx];
                        #pragma unroll
                        for (int o = 0; o < 8; o++)
                            asm("fma.rn.f32x2 %0, %1, %2, %0;"
                                : "+l"(acc[r][o]) : "l"(vv), "l"(w[o]));
                    }
                }
            }
        }

        // store (coalesced over tx)
        #pragma unroll
        for (int o = 0; o < 8; o++) {
            #pragma unroll
            for (int r = 0; r < 4; r++) {
                const float2 f = *reinterpret_cast<const float2*>(&acc[r][o]);
                const int gy = ty0 + ybase + r;
                const int gx = tx0 + tx;
                out[((size_t)(b * OUTC + ocg + 2 * o))     * HW + gy * WW + gx] = f.x;
                out[((size_t)(b * OUTC + ocg + 2 * o + 1)) * HW + gy * WW + gx] = f.y;
            }
        }
    }
}

// ===================================================================
extern "C" void kernel_launch(void* const* d_in, const int* in_sizes, int n_in,
                              void* d_out, int out_size) {
    const float* x    = (const float*)d_in[0];   // [8,64,256,256]
    const float* wgt  = (const float*)d_in[1];   // [64,16,3,3]
    const float* bias = (const float*)d_in[2];   // [64]
    float* out = (float*)d_out;                  // [8,112,256,256]

    cudaFuncSetAttribute(hist_entropy_kernel,
                         cudaFuncAttributeMaxDynamicSharedMemorySize, 256 * NBINS * 2);
    cudaFuncSetAttribute(conv_kernel,
                         cudaFuncAttributeMaxDynamicSharedMemorySize, CONV_SMEM);

    hist_entropy_kernel<<<BATCH * CH, 256, 256 * NBINS * 2>>>(x);
    topk_kernel<<<1, 32>>>();
    copy_untouched_kernel<<<dim3(64, BATCH * NUNSEL), 256>>>(x, out);
    conv_kernel<<<dim3(64, BATCH), 256, CONV_SMEM>>>(x, wgt, bias, out);
}

// round 9
// speedup vs baseline: 1.3350x; 1.2339x over previous
#include <cuda_runtime.h>
#include <math.h>
#include <stdint.h>

#define BATCH 8
#define CH    64
#define HH    256
#define WW    256
#define HW    65536
#define P     16
#define OC    64
#define NUNSEL 48
#define OUTC  112   // OC + (CH - P)
#define NBINS 256

typedef unsigned long long ull;

// ---------------- device scratch (no allocation allowed) ----------------
__device__ double g_ent[BATCH * CH];
__device__ int    g_sel[BATCH][P];
__device__ int    g_unsel[BATCH][NUNSEL];

// ===================================================================
// Kernel 1: per-(b,c) min/max + privatized 256-bin histogram + entropy
// one block per (b,c). 256 threads x 256 u8 bins = 64KB -> 3 CTAs/SM.
// Per-thread element count is 256, so u8 cannot wrap (needs 256 identical
// bins). Rotation bin' = (bin + 4*tid) & 255 -> bank ((bin>>2)+tid)&31:
// conflict-free when lanes share a bin.
// ===================================================================
__global__ __launch_bounds__(256) void hist_entropy_kernel(const float* __restrict__ x) {
    extern __shared__ unsigned char s_hist[];   // [tid][rot(bin)], 256*256 u8
    __shared__ float  s_mn[256];
    __shared__ float  s_mx[256];
    __shared__ double s_d[256];

    const int bc  = blockIdx.x;          // 0..511
    const int tid = threadIdx.x;
    const float4* xp = (const float4*)(x + (size_t)bc * HW);

    // zero private histograms (65536 u8 = 4096 uint4)
    {
        uint4* h4 = (uint4*)s_hist;
        #pragma unroll
        for (int i = 0; i < 16; i++) h4[tid + i * 256] = make_uint4(0u, 0u, 0u, 0u);
    }

    // ---- pass 1: min/max (2-way unrolled for MLP) ----
    float mn =  3.4e38f, mx = -3.4e38f;
    for (int i = tid; i < HW / 4; i += 512) {
        float4 a = xp[i];
        float4 b = xp[i + 256];
        mn = fminf(mn, fminf(fminf(a.x, a.y), fminf(a.z, a.w)));
        mx = fmaxf(mx, fmaxf(fmaxf(a.x, a.y), fmaxf(a.z, a.w)));
        mn = fminf(mn, fminf(fminf(b.x, b.y), fminf(b.z, b.w)));
        mx = fmaxf(mx, fmaxf(fmaxf(b.x, b.y), fmaxf(b.z, b.w)));
    }
    s_mn[tid] = mn; s_mx[tid] = mx;
    __syncthreads();
    for (int s = 128; s > 0; s >>= 1) {
        if (tid < s) {
            s_mn[tid] = fminf(s_mn[tid], s_mn[tid + s]);
            s_mx[tid] = fmaxf(s_mx[tid], s_mx[tid + s]);
        }
        __syncthreads();
    }
    mn = s_mn[0];
    mx = s_mx[0];

    // ---- pass 2: binning into swizzled private u8 histogram (no atomics) ----
    // Must match XLA bit-exactly: (x - min) / ((max - min) + 1e-8f), *256, trunc, clip.
    const float den = (mx - mn) + 1e-8f;
    const int rot = tid << 2;
    unsigned char* my = s_hist + tid * NBINS;
    for (int i = tid; i < HW / 4; i += 512) {
        float4 va = xp[i];
        float4 vb = xp[i + 256];
        float f0 = __fdiv_rn(va.x - mn, den);
        float f1 = __fdiv_rn(va.y - mn, den);
        float f2 = __fdiv_rn(va.z - mn, den);
        float f3 = __fdiv_rn(va.w - mn, den);
        float f4 = __fdiv_rn(vb.x - mn, den);
        float f5 = __fdiv_rn(vb.y - mn, den);
        float f6 = __fdiv_rn(vb.z - mn, den);
        float f7 = __fdiv_rn(vb.w - mn, den);
        int b0 = min(max((int)(f0 * 256.0f), 0), NBINS - 1);
        int b1 = min(max((int)(f1 * 256.0f), 0), NBINS - 1);
        int b2 = min(max((int)(f2 * 256.0f), 0), NBINS - 1);
        int b3 = min(max((int)(f3 * 256.0f), 0), NBINS - 1);
        int b4 = min(max((int)(f4 * 256.0f), 0), NBINS - 1);
        int b5 = min(max((int)(f5 * 256.0f), 0), NBINS - 1);
        int b6 = min(max((int)(f6 * 256.0f), 0), NBINS - 1);
        int b7 = min(max((int)(f7 * 256.0f), 0), NBINS - 1);
        my[(b0 + rot) & 255]++;
        my[(b1 + rot) & 255]++;
        my[(b2 + rot) & 255]++;
        my[(b3 + rot) & 255]++;
        my[(b4 + rot) & 255]++;
        my[(b5 + rot) & 255]++;
        my[(b6 + rot) & 255]++;
        my[(b7 + rot) & 255]++;
    }
    __syncthreads();

    // ---- flush: count for bin 'tid' = sum over all 256 private (rotated) copies ----
    unsigned int cnt = 0;
    #pragma unroll 8
    for (int t = 0; t < 256; t++)
        cnt += (unsigned int)s_hist[t * NBINS + ((tid + (t << 2)) & 255)];

    // ---- entropy (double; preserves f32-reference ordering with margin) ----
    double h = (cnt > 0) ? (double)cnt : 1e-8;
    s_d[tid] = h;
    __syncthreads();
    for (int s = 128; s > 0; s >>= 1) {
        if (tid < s) s_d[tid] += s_d[tid + s];
        __syncthreads();
    }
    double sum = s_d[0];
    __syncthreads();
    double p = h / sum;
    s_d[tid] = -p * log(p + 1e-8);
    __syncthreads();
    for (int s = 128; s > 0; s >>= 1) {
        if (tid < s) s_d[tid] += s_d[tid + s];
        __syncthreads();
    }
    if (tid == 0) g_ent[bc] = s_d[0];
}

// ===================================================================
// Kernel 2: top-16 per batch (strict >, ties -> lowest index, = jax top_k)
// entropies staged in smem to kill serial gmem latency.
// ===================================================================
__global__ __launch_bounds__(256) void topk_kernel() {
    __shared__ double se[BATCH * CH];
    const int tid = threadIdx.x;
    for (int i = tid; i < BATCH * CH; i += 256) se[i] = g_ent[i];
    __syncthreads();
    if (tid < BATCH) {
        const int b = tid;
        bool used[CH];
        #pragma unroll
        for (int c = 0; c < CH; c++) used[c] = false;
        for (int p = 0; p < P; p++) {
            int best = -1;
            double bv = -1e300;
            for (int c = 0; c < CH; c++) {
                if (!used[c]) {
                    double e = se[b * CH + c];
                    if (e > bv) { bv = e; best = c; }
                }
            }
            g_sel[b][p] = best;
            used[best] = true;
        }
        int j = 0;
        for (int c = 0; c < CH; c++)
            if (!used[c]) g_unsel[b][j++] = c;
    }
}

// ===================================================================
// Kernel 3: copy untouched channels (ascending order) to out[:, 64:112]
// (overlapped with conv on a forked stream — pure DRAM vs pure FMA)
// ===================================================================
__global__ __launch_bounds__(256) void copy_untouched_kernel(const float* __restrict__ x,
                                                             float* __restrict__ out) {
    const int j = blockIdx.y;            // 0..383
    const int b = j / NUNSEL;
    const int u = j - b * NUNSEL;
    const int src_c = g_unsel[b][u];
    const float4* s = (const float4*)(x + ((size_t)(b * CH + src_c)) * HW);
    float4*       d = (float4*)(out + ((size_t)(b * OUTC + OC + u)) * HW);
    const int i = blockIdx.x * 256 + threadIdx.x;   // gridDim.x = 64 -> 16384 f4
    d[i] = s[i];
}

// ===================================================================
// Kernel 4: direct 3x3 conv via packed fma.rn.f32x2, 3 CTAs/SM.
// block = one (batch, 32x16 tile). Each thread: 2 rows x 16 oc.
// smem: input 16ic x 18 x 34 (38.25KB) + one 16-oc weight chunk
// [144][16] (9KB) -> 48384B/CTA -> 3 CTAs/SM; regs capped for occ=3.
// ===================================================================
#define TIN_H 18
#define TIN_W 34
#define SIN_ELEMS (16 * TIN_H * TIN_W)   // 9792
#define SWC_ELEMS (144 * 16)             // 2304 (one 16-oc chunk)
#define CONV_SMEM ((SIN_ELEMS + SWC_ELEMS) * 4)   // 48384

__global__ __launch_bounds__(256, 3) void conv_kernel(const float* __restrict__ x,
                                                      const float* __restrict__ wgt,
                                                      const float* __restrict__ bias,
                                                      float* __restrict__ out) {
    extern __shared__ float smem[];
    float* s_in = smem;                  // [ic][18][34]
    float* s_w  = smem + SIN_ELEMS;      // [(ic*9+ky*3+kx)][16]

    const int b       = blockIdx.y;
    const int tileIdx = blockIdx.x;      // 0..127 : 16 tile-rows x 8 tile-cols
    const int ty0 = (tileIdx >> 3) << 4;
    const int tx0 = (tileIdx & 7) << 5;
    const int tid = threadIdx.x;

    // stage input tile with halo (zero padding at image borders)
    for (int i = tid; i < SIN_ELEMS; i += 256) {
        const int ic = i / (TIN_H * TIN_W);
        const int r  = i - ic * (TIN_H * TIN_W);
        const int yy = r / TIN_W;
        const int xx = r - yy * TIN_W;
        const int gy = ty0 + yy - 1;
        const int gx = tx0 + xx - 1;
        float v = 0.0f;
        if (gy >= 0 && gy < HH && gx >= 0 && gx < WW) {
            const int c = g_sel[b][ic];
            v = __ldg(&x[((size_t)(b * CH + c)) * HW + gy * WW + gx]);
        }
        s_in[i] = v;
    }

    const int tx    = tid & 31;
    const int warp  = tid >> 5;     // 0..7
    const int ybase = warp << 1;    // output rows ybase, ybase+1 (tile-local)

    for (int ocg = 0; ocg < OC; ocg += 16) {
        __syncthreads();   // protect s_w from previous iteration's readers
        // stage this ocg's weights transposed: s_w[r*16 + ol] = wgt[(ocg+ol)*144 + r]
        for (int i = tid; i < SWC_ELEMS; i += 256) {
            const int r  = i >> 4;
            const int ol = i & 15;
            s_w[i] = __ldg(&wgt[(ocg + ol) * 144 + r]);
        }
        __syncthreads();

        // acc[r][o] holds oc = ocg+2o (low) and ocg+2o+1 (high)
        ull acc[2][8];
        {
            const ull* bp = (const ull*)(bias + ocg);   // 8B-aligned
            #pragma unroll
            for (int o = 0; o < 8; o++) {
                const ull bb = __ldg(&bp[o]);
                acc[0][o] = bb;
                acc[1][o] = bb;
            }
        }

        for (int ic = 0; ic < P; ic++) {
            const float* si = s_in + ic * (TIN_H * TIN_W);
            // 4 rows x 3 cols window, duplicate-packed (rows reused across ky)
            ull vinp[4][3];
            #pragma unroll
            for (int j = 0; j < 4; j++) {
                #pragma unroll
                for (int kx = 0; kx < 3; kx++) {
                    const float v = si[(ybase + j) * TIN_W + tx + kx];
                    asm("mov.b64 %0, {%1, %1};" : "=l"(vinp[j][kx]) : "f"(v));
                }
            }
            const float* wb = s_w + ic * 9 * 16;
            #pragma unroll
            for (int ky = 0; ky < 3; ky++) {
                #pragma unroll
                for (int kx = 0; kx < 3; kx++) {
                    // 16 weights (8 f32x2 pairs) via 2 broadcast LDS.128
                    const ulonglong2* wp = (const ulonglong2*)(wb + (ky * 3 + kx) * 16);
                    ulonglong2 w0 = wp[0];
                    ulonglong2 w1 = wp[1];
                    ulonglong2 w2 = wp[2];
                    ulonglong2 w3 = wp[3];
                    const ull w[8] = {w0.x, w0.y, w1.x, w1.y, w2.x, w2.y, w3.x, w3.y};
                    #pragma unroll
                    for (int r = 0; r < 2; r++) {
                        const ull vv = vinp[r + ky][kx];
                        #pragma unroll
                        for (int o = 0; o < 8; o++)
                            asm("fma.rn.f32x2 %0, %1, %2, %0;"
                                : "+l"(acc[r][o]) : "l"(vv), "l"(w[o]));
                    }
                }
            }
        }

        // store (coalesced over tx)
        #pragma unroll
        for (int o = 0; o < 8; o++) {
            #pragma unroll
            for (int r = 0; r < 2; r++) {
                const float2 f = *reinterpret_cast<const float2*>(&acc[r][o]);
                const int gy = ty0 + ybase + r;
                const int gx = tx0 + tx;
                out[((size_t)(b * OUTC + ocg + 2 * o))     * HW + gy * WW + gx] = f.x;
                out[((size_t)(b * OUTC + ocg + 2 * o + 1)) * HW + gy * WW + gx] = f.y;
            }
        }
    }
}

// ===================================================================
extern "C" void kernel_launch(void* const* d_in, const int* in_sizes, int n_in,
                              void* d_out, int out_size) {
    const float* x    = (const float*)d_in[0];   // [8,64,256,256]
    const float* wgt  = (const float*)d_in[1];   // [64,16,3,3]
    const float* bias = (const float*)d_in[2];   // [64]
    float* out = (float*)d_out;                  // [8,112,256,256]

    // Lazy one-time stream/event creation (first call is the uncaptured
    // correctness run; capture sees only launches + event fork/join nodes).
    static cudaStream_t s_side = nullptr;
    static cudaEvent_t  e_fork = nullptr, e_join = nullptr;
    static bool attr_done = false;
    if (!s_side) {
        cudaStreamCreateWithFlags(&s_side, cudaStreamNonBlocking);
        cudaEventCreateWithFlags(&e_fork, cudaEventDisableTiming);
        cudaEventCreateWithFlags(&e_join, cudaEventDisableTiming);
    }
    if (!attr_done) {
        cudaFuncSetAttribute(hist_entropy_kernel,
                             cudaFuncAttributeMaxDynamicSharedMemorySize, 256 * NBINS);
        cudaFuncSetAttribute(conv_kernel,
                             cudaFuncAttributeMaxDynamicSharedMemorySize, CONV_SMEM);
        attr_done = true;
    }

    hist_entropy_kernel<<<BATCH * CH, 256, 256 * NBINS>>>(x);
    topk_kernel<<<1, 256>>>();

    // fork: copy (DRAM-bound) runs concurrently with conv (FMA-bound)
    cudaEventRecord(e_fork, 0);
    cudaStreamWaitEvent(s_side, e_fork, 0);
    copy_untouched_kernel<<<dim3(64, BATCH * NUNSEL), 256, 0, s_side>>>(x, out);
    cudaEventRecord(e_join, s_side);

    conv_kernel<<<dim3(128, BATCH), 256, CONV_SMEM>>>(x, wgt, bias, out);
    cudaStreamWaitEvent(0, e_join, 0);
}